// round 12
// baseline (speedup 1.0000x reference)
#include <cuda_runtime.h>
#include <cstdint>

// Chamfer distance, B=4,S=4 pairs, N=M=4096 Gaussian 3D points.
// Warp-uniform growing-rectangle exact NN over a 64x64 (x,y) cell grid,
// with MORTON-ordered queries for 2-D compact warps:
//  1) build_cells: per list, (a) counting-sort into 64x64 cells
//     (x-major, y-minor) -> packed 32B records {x0,x1,y0,y1,z0,z1,h0,h1}
//     + u16 cell starts (target layout, contiguous per column-range);
//     (b) counting-sort the same points by Morton(cx,cy) -> float4 copy
//     (query order: 32 consecutive queries = compact 2-D patch).
//  2) chamfer_query: block stages packed targets (64KB) + cell starts
//     (8KB) in smem. Warp = 32 consecutive Morton-ordered queries; scans
//     its union cell-rectangle column-by-column (contiguous ranges,
//     2xLDS.128 + 3xFMA2 + 2xFMNMX per 2 targets), then ballot-expands
//     any uncertified edge. Exact via rectangle-edge distance bounds.

#define BDIM 4
#define SDIM 4
#define NPAIRS 16
#define NBX 64
#define NCELL (NBX * NBX)
#define MAXPTS 4096
#define NREC ((MAXPTS + 8) / 2)   /* 2052 records of 2 points */
#define GRIDMIN (-5.0f)
#define CW 0.15625f               /* 10/64 */
#define INVCW 6.4f
#define QTHREADS 256

__device__ float g_packed[2 * NPAIRS][NREC * 8];          // column-sorted targets
__device__ float4 g_qsorted[2 * NPAIRS][MAXPTS];          // Morton-sorted queries
__device__ unsigned short g_start[2 * NPAIRS][NCELL + 1];

__device__ __forceinline__ uint64_t fma2(uint64_t a, uint64_t b, uint64_t c) {
    uint64_t d;
    asm("fma.rn.f32x2 %0, %1, %2, %3;" : "=l"(d) : "l"(a), "l"(b), "l"(c));
    return d;
}
__device__ __forceinline__ uint64_t pack2(float lo, float hi) {
    uint64_t d;
    asm("mov.b64 %0, {%1, %2};" : "=l"(d) : "f"(lo), "f"(hi));
    return d;
}
__device__ __forceinline__ void unpack2(uint64_t v, float& lo, float& hi) {
    asm("mov.b64 {%0, %1}, %2;" : "=f"(lo), "=f"(hi) : "l"(v));
}
__device__ __forceinline__ unsigned part1by1(unsigned x) {
    x &= 0xFFFF;
    x = (x | (x << 8)) & 0x00FF00FF;
    x = (x | (x << 4)) & 0x0F0F0F0F;
    x = (x | (x << 2)) & 0x33333333;
    x = (x | (x << 1)) & 0x55555555;
    return x;
}

// ---------------- build: column sort + Morton sort ----------------
__global__ void build_cells(const float* __restrict__ outp,
                            const float* __restrict__ tgtp,
                            int Nq, int Mt, float* __restrict__ out) {
    const int list = blockIdx.x;             // 0..31
    const int set = list >> 4, pair = list & 15;
    const float* pts = set ? tgtp : outp;
    const int n = set ? Mt : Nq;
    const float* base = pts + (size_t)pair * n * 3;

    if (list == 0 && threadIdx.x < BDIM * SDIM) out[threadIdx.x] = 0.f;

    __shared__ int cnt[NCELL];
    __shared__ int partial[256];
    const int t = threadIdx.x;               // 256 threads

    // ---------- pass A: column order (cx*64 + cy) ----------
    for (int c = t; c < NCELL; c += 256) cnt[c] = 0;
    __syncthreads();
    for (int i = t; i < n; i += 256) {
        float x = base[3 * i], y = base[3 * i + 1];
        int cx = min(max(__float2int_rd((x - GRIDMIN) * INVCW), 0), NBX - 1);
        int cy = min(max(__float2int_rd((y - GRIDMIN) * INVCW), 0), NBX - 1);
        atomicAdd(&cnt[cx * NBX + cy], 1);
    }
    __syncthreads();
    {
        int csum = 0;
#pragma unroll
        for (int j = 0; j < 16; j++) csum += cnt[t * 16 + j];
        partial[t] = csum;
        __syncthreads();
        for (int off = 1; off < 256; off <<= 1) {
            int v = (t >= off) ? partial[t - off] : 0;
            __syncthreads();
            partial[t] += v;
            __syncthreads();
        }
        int run = (t == 0) ? 0 : partial[t - 1];
#pragma unroll
        for (int j = 0; j < 16; j++) {
            int c = t * 16 + j;
            int v = cnt[c];
            cnt[c] = run;
            run += v;
        }
    }
    __syncthreads();
    for (int c = t; c < NCELL; c += 256)
        g_start[list][c] = (unsigned short)cnt[c];
    if (t == 0) g_start[list][NCELL] = (unsigned short)n;
    __syncthreads();
    for (int i = t; i < n; i += 256) {
        float x = base[3 * i], y = base[3 * i + 1], z = base[3 * i + 2];
        int cx = min(max(__float2int_rd((x - GRIDMIN) * INVCW), 0), NBX - 1);
        int cy = min(max(__float2int_rd((y - GRIDMIN) * INVCW), 0), NBX - 1);
        int idx = atomicAdd(&cnt[cx * NBX + cy], 1);
        float* rec = &g_packed[list][(idx >> 1) * 8];
        int s = idx & 1;
        rec[0 + s] = x;
        rec[2 + s] = y;
        rec[4 + s] = z;
        rec[6 + s] = 0.5f * (x * x + y * y + z * z);
    }
    for (int i = n + t; i < 2 * NREC; i += 256) {
        float* rec = &g_packed[list][(i >> 1) * 8];
        int s = i & 1;
        rec[0 + s] = 1e30f;
        rec[2 + s] = 0.f;
        rec[4 + s] = 0.f;
        rec[6 + s] = 3.0e37f;
    }
    __syncthreads();

    // ---------- pass B: Morton order (queries) ----------
    for (int c = t; c < NCELL; c += 256) cnt[c] = 0;
    __syncthreads();
    for (int i = t; i < n; i += 256) {
        float x = base[3 * i], y = base[3 * i + 1];
        int cx = min(max(__float2int_rd((x - GRIDMIN) * INVCW), 0), NBX - 1);
        int cy = min(max(__float2int_rd((y - GRIDMIN) * INVCW), 0), NBX - 1);
        unsigned code = part1by1((unsigned)cx) | (part1by1((unsigned)cy) << 1);
        atomicAdd(&cnt[code], 1);
    }
    __syncthreads();
    {
        int csum = 0;
#pragma unroll
        for (int j = 0; j < 16; j++) csum += cnt[t * 16 + j];
        partial[t] = csum;
        __syncthreads();
        for (int off = 1; off < 256; off <<= 1) {
            int v = (t >= off) ? partial[t - off] : 0;
            __syncthreads();
            partial[t] += v;
            __syncthreads();
        }
        int run = (t == 0) ? 0 : partial[t - 1];
#pragma unroll
        for (int j = 0; j < 16; j++) {
            int c = t * 16 + j;
            int v = cnt[c];
            cnt[c] = run;
            run += v;
        }
    }
    __syncthreads();
    for (int i = t; i < n; i += 256) {
        float x = base[3 * i], y = base[3 * i + 1], z = base[3 * i + 2];
        int cx = min(max(__float2int_rd((x - GRIDMIN) * INVCW), 0), NBX - 1);
        int cy = min(max(__float2int_rd((y - GRIDMIN) * INVCW), 0), NBX - 1);
        unsigned code = part1by1((unsigned)cx) | (part1by1((unsigned)cy) << 1);
        int idx = atomicAdd(&cnt[code], 1);
        g_qsorted[list][idx] = make_float4(x, y, z, 0.f);
    }
}

// ---------------- query ----------------
extern __shared__ char smraw[];

// warp-uniform scan of even point range [a,b); each lane its own min
__device__ __forceinline__ void scan_range(
    int a, int b,
    uint64_t nx, uint64_t ny, uint64_t nz,
    const ulonglong2* __restrict__ recs,
    float& mlo, float& mhi) {
    const int j0 = a >> 1, j1 = b >> 1;
#pragma unroll 4
    for (int j = j0; j < j1; j++) {
        ulonglong2 A = recs[2 * j];      // {x2, y2}
        ulonglong2 B = recs[2 * j + 1];  // {z2, h2}
        uint64_t t = fma2(nx, A.x, B.y);
        t = fma2(ny, A.y, t);
        t = fma2(nz, B.x, t);
        float lo, hi;
        unpack2(t, lo, hi);
        mlo = fminf(mlo, lo);
        mhi = fminf(mhi, hi);
    }
}

__global__ __launch_bounds__(QTHREADS)
void chamfer_query(int Nq, int Mt, float* __restrict__ out) {
    const int dir = blockIdx.z;             // 0: out->tgt, 1: tgt->out
    const int pair = blockIdx.y;
    const int qlist = (dir ? NPAIRS : 0) + pair;      // own set (Morton copy)
    const int tlist = (dir ? 0 : NPAIRS) + pair;      // other set (columns)
    const int nq = dir ? Mt : Nq;

    // ---- stage packed target records (64KB) + cell starts (8KB) ----
    uint4* dst = (uint4*)smraw;
    const uint4* src = (const uint4*)g_packed[tlist];
    for (int i = threadIdx.x; i < 2 * NREC; i += QTHREADS)
        dst[i] = src[i];
    unsigned short* sstart = (unsigned short*)(smraw + NREC * 32);
    for (int c = threadIdx.x; c <= NCELL; c += QTHREADS)
        sstart[c] = g_start[tlist][c];
    __syncthreads();

    const ulonglong2* recs = (const ulonglong2*)smraw;

    const int qi = blockIdx.x * QTHREADS + threadIdx.x;
    const bool active = (qi < nq);

    float qx = 0.f, qy = 0.f, q2 = 0.f;
    uint64_t nx = 0, ny = 0, nz = 0;
    int cxm = 0x7fffffff, cxM = -1, cym = 0x7fffffff, cyM = -1;
    if (active) {
        float4 q = g_qsorted[qlist][qi];   // Morton order: compact warps
        qx = q.x;
        qy = q.y;
        q2 = qx * qx + qy * qy + q.z * q.z;
        nx = pack2(-qx, -qx);
        ny = pack2(-qy, -qy);
        nz = pack2(-q.z, -q.z);
        int cx = min(max(__float2int_rd((qx - GRIDMIN) * INVCW), 0), NBX - 1);
        int cy = min(max(__float2int_rd((qy - GRIDMIN) * INVCW), 0), NBX - 1);
        cxm = cx; cxM = cx; cym = cy; cyM = cy;
    }
    float mlo = 3.0e37f, mhi = 3.0e37f;

    // warp-union cell rectangle
    int XL = cxm, XR = cxM, YL = cym, YH = cyM;
#pragma unroll
    for (int off = 16; off; off >>= 1) {
        XL = min(XL, __shfl_xor_sync(0xffffffffu, XL, off));
        XR = max(XR, __shfl_xor_sync(0xffffffffu, XR, off));
        YL = min(YL, __shfl_xor_sync(0xffffffffu, YL, off));
        YH = max(YH, __shfl_xor_sync(0xffffffffu, YH, off));
    }

    if (XR >= 0) {  // warp has at least one active lane
        XL = max(XL - 1, 0);
        XR = min(XR + 1, NBX - 1);
        YL = max(YL - 1, 0);
        YH = min(YH + 1, NBX - 1);

        // initial rectangle scan (one contiguous range per x-column)
        for (int xb = XL; xb <= XR; xb++) {
            int a = sstart[xb * NBX + YL] & ~1;
            int b = (sstart[xb * NBX + YH + 1] + 1) & ~1;
            scan_range(a, b, nx, ny, nz, recs, mlo, mhi);
        }

        // ---- ballot-driven rectangle expansion ----
        for (int iter = 0; iter < 2 * NBX; iter++) {
            float best = fmaxf(fmaf(2.0f, fminf(mlo, mhi), q2), 0.0f);
            float dl = fmaxf(qx - (GRIDMIN + XL * CW) - 1e-4f, 0.0f);
            float dr = fmaxf((GRIDMIN + (XR + 1) * CW) - qx - 1e-4f, 0.0f);
            float dd = fmaxf(qy - (GRIDMIN + YL * CW) - 1e-4f, 0.0f);
            float du = fmaxf((GRIDMIN + (YH + 1) * CW) - qy - 1e-4f, 0.0f);
            bool nL = active && (XL > 0)       && (dl * dl < best);
            bool nR = active && (XR < NBX - 1) && (dr * dr < best);
            bool nD = active && (YL > 0)       && (dd * dd < best);
            bool nU = active && (YH < NBX - 1) && (du * du < best);
            unsigned aL = __ballot_sync(0xffffffffu, nL);
            unsigned aR = __ballot_sync(0xffffffffu, nR);
            unsigned aD = __ballot_sync(0xffffffffu, nD);
            unsigned aU = __ballot_sync(0xffffffffu, nU);
            if (!(aL | aR | aD | aU)) break;
            if (aL) {
                XL--;
                int a = sstart[XL * NBX + YL] & ~1;
                int b = (sstart[XL * NBX + YH + 1] + 1) & ~1;
                scan_range(a, b, nx, ny, nz, recs, mlo, mhi);
            }
            if (aR) {
                XR++;
                int a = sstart[XR * NBX + YL] & ~1;
                int b = (sstart[XR * NBX + YH + 1] + 1) & ~1;
                scan_range(a, b, nx, ny, nz, recs, mlo, mhi);
            }
            if (aD) {
                YL--;
                for (int xb = XL; xb <= XR; xb++) {
                    int a = sstart[xb * NBX + YL] & ~1;
                    int b = (sstart[xb * NBX + YL + 1] + 1) & ~1;
                    scan_range(a, b, nx, ny, nz, recs, mlo, mhi);
                }
            }
            if (aU) {
                YH++;
                for (int xb = XL; xb <= XR; xb++) {
                    int a = sstart[xb * NBX + YH] & ~1;
                    int b = (sstart[xb * NBX + YH + 1] + 1) & ~1;
                    scan_range(a, b, nx, ny, nz, recs, mlo, mhi);
                }
            }
        }
    }

    float lsum = active ? fmaxf(fmaf(2.0f, fminf(mlo, mhi), q2), 0.0f) : 0.f;

    // ---- block reduce + one atomicAdd ----
#pragma unroll
    for (int off = 16; off; off >>= 1)
        lsum += __shfl_down_sync(0xffffffffu, lsum, off);
    __shared__ float red[QTHREADS / 32];
    const int lwid = threadIdx.x >> 5;
    if ((threadIdx.x & 31) == 0) red[lwid] = lsum;
    __syncthreads();
    if (threadIdx.x == 0) {
        float tot = 0.f;
#pragma unroll
        for (int w = 0; w < QTHREADS / 32; w++) tot += red[w];
        int b = pair / SDIM;
        int s = pair % SDIM;
        atomicAdd(out + s * BDIM + b, tot / (float)nq);
    }
}

extern "C" void kernel_launch(void* const* d_in, const int* in_sizes, int n_in,
                              void* d_out, int out_size) {
    const float* outp = (const float*)d_in[0];  // [B,S,N,3]
    const float* tgtp = (const float*)d_in[1];  // [B,S,M,3]
    float* out = (float*)d_out;                  // [S,B]

    const int Nq = in_sizes[0] / (NPAIRS * 3);
    const int Mt = in_sizes[1] / (NPAIRS * 3);

    build_cells<<<2 * NPAIRS, 256>>>(outp, tgtp, Nq, Mt, out);

    const size_t smem = (size_t)NREC * 32 +
                        (NCELL + 2) * sizeof(unsigned short);
    cudaFuncSetAttribute(chamfer_query,
                         cudaFuncAttributeMaxDynamicSharedMemorySize, (int)smem);

    const int maxq = Nq > Mt ? Nq : Mt;
    dim3 grid((maxq + QTHREADS - 1) / QTHREADS, NPAIRS, 2);  // 512 blocks
    chamfer_query<<<grid, QTHREADS, smem>>>(Nq, Mt, out);
}

// round 13
// speedup vs baseline: 2.0482x; 2.0482x over previous
#include <cuda_runtime.h>
#include <cstdint>

// Chamfer distance, B=4,S=4 pairs, N=M=4096 Gaussian 3D points.
// Warp-uniform 1-D sorted-window exact NN. QPT=2 + 256-thread blocks:
//  1) build_sorted: counting-sort the 32 lists by x into 256 bins over
//     [-5,5]; emits interleaved 32B records {x0,x1,y0,y1,z0,z1,h0,h1}
//     (h = 0.5*|p|^2) + u16 bin starts. Also zeroes d_out (block 0).
//  2) chamfer_query: block stages the packed target list (64KB) in smem.
//     Each warp owns 64 consecutive sorted queries (lane k: base+k and
//     base+32+k) -> 2 independent fma2 chains per lane. 8 warps/block,
//     stride-8 warp->query-group mapping balances block workloads.
//     Inner loop: 2x LDS.128 + 6x fma.rn.f32x2 + 4x FMNMX per record.
//     Ballot-driven exact expansion via bin-edge bounds.

#define BDIM 4
#define SDIM 4
#define NPAIRS 16
#define NB 256
#define MAXPTS 4096
#define NREC ((MAXPTS + 8) / 2)   /* 2052 records of 2 points */
#define GRIDMIN (-5.0f)
#define BW 0.0390625f             /* 10/256 */
#define INVBW 25.6f
#define QTHREADS 256
#define QPT 2
#define NCHUNK 8                  /* blocks per (dir,pair): 8*8 warps = 64 qgroups */

__device__ float g_packed[2 * NPAIRS][NREC * 8];
__device__ unsigned short g_start[2 * NPAIRS][NB + 1];

__device__ __forceinline__ uint64_t fma2(uint64_t a, uint64_t b, uint64_t c) {
    uint64_t d;
    asm("fma.rn.f32x2 %0, %1, %2, %3;" : "=l"(d) : "l"(a), "l"(b), "l"(c));
    return d;
}
__device__ __forceinline__ uint64_t pack2(float lo, float hi) {
    uint64_t d;
    asm("mov.b64 %0, {%1, %2};" : "=l"(d) : "f"(lo), "f"(hi));
    return d;
}
__device__ __forceinline__ void unpack2(uint64_t v, float& lo, float& hi) {
    asm("mov.b64 {%0, %1}, %2;" : "=f"(lo), "=f"(hi) : "l"(v));
}

// ---------------- counting sort by x into 256 bins ----------------
__global__ void build_sorted(const float* __restrict__ outp,
                             const float* __restrict__ tgtp,
                             int Nq, int Mt, float* __restrict__ out) {
    const int list = blockIdx.x;            // 0..31
    const int set = list >> 4, pair = list & 15;
    const float* pts = set ? tgtp : outp;
    const int n = set ? Mt : Nq;
    const float* base = pts + (size_t)pair * n * 3;

    if (list == 0 && threadIdx.x < BDIM * SDIM) out[threadIdx.x] = 0.f;

    __shared__ int cnt[NB];
    const int t = threadIdx.x;              // 256 threads

    cnt[t] = 0;
    __syncthreads();

    for (int i = t; i < n; i += NB) {
        float x = base[3 * i];
        int b = min(max(__float2int_rd((x - GRIDMIN) * INVBW), 0), NB - 1);
        atomicAdd(&cnt[b], 1);
    }
    __syncthreads();

    int v = cnt[t];
    __syncthreads();
#pragma unroll
    for (int off = 1; off < NB; off <<= 1) {
        int u = (t >= off) ? cnt[t - off] : 0;
        __syncthreads();
        cnt[t] += u;
        __syncthreads();
    }
    int start = cnt[t] - v;  // exclusive

    g_start[list][t] = (unsigned short)start;
    if (t == 0) g_start[list][NB] = (unsigned short)n;

    __syncthreads();
    cnt[t] = start;
    __syncthreads();

    for (int i = t; i < n; i += NB) {
        float x = base[3 * i], y = base[3 * i + 1], z = base[3 * i + 2];
        int b = min(max(__float2int_rd((x - GRIDMIN) * INVBW), 0), NB - 1);
        int idx = atomicAdd(&cnt[b], 1);
        float* rec = &g_packed[list][(idx >> 1) * 8];
        int s = idx & 1;
        rec[0 + s] = x;
        rec[2 + s] = y;
        rec[4 + s] = z;
        rec[6 + s] = 0.5f * (x * x + y * y + z * z);
    }
    // sentinel pad points [n, 2*NREC)
    for (int i = n + t; i < 2 * NREC; i += NB) {
        float* rec = &g_packed[list][(i >> 1) * 8];
        int s = i & 1;
        rec[0 + s] = 1e30f;
        rec[2 + s] = 0.f;
        rec[4 + s] = 0.f;
        rec[6 + s] = 3.0e37f;
    }
}

// ---------------- query ----------------
extern __shared__ char smraw[];

// warp-uniform scan of even point range [a,b); QPT independent chains/lane
__device__ __forceinline__ void scan_range(
    int a, int b,
    const uint64_t* nx, const uint64_t* ny, const uint64_t* nz,
    const ulonglong2* __restrict__ recs,
    float* mlo, float* mhi) {
    const int j0 = a >> 1, j1 = b >> 1;
#pragma unroll 2
    for (int j = j0; j < j1; j++) {
        ulonglong2 A = recs[2 * j];      // {x2, y2}
        ulonglong2 B = recs[2 * j + 1];  // {z2, h2}
#pragma unroll
        for (int k = 0; k < QPT; k++) {
            uint64_t t = fma2(nx[k], A.x, B.y);
            t = fma2(ny[k], A.y, t);
            t = fma2(nz[k], B.x, t);
            float lo, hi;
            unpack2(t, lo, hi);
            mlo[k] = fminf(mlo[k], lo);
            mhi[k] = fminf(mhi[k], hi);
        }
    }
}

__global__ __launch_bounds__(QTHREADS)
void chamfer_query(int Nq, int Mt, float* __restrict__ out) {
    const int dir = blockIdx.z;             // 0: out->tgt, 1: tgt->out
    const int pair = blockIdx.y;
    const int qlist = (dir ? NPAIRS : 0) + pair;      // own (sorted) set
    const int tlist = (dir ? 0 : NPAIRS) + pair;      // other set
    const int nq = dir ? Mt : Nq;

    // ---- stage packed target records (64KB copy) + bin starts ----
    uint4* dst = (uint4*)smraw;
    const uint4* src = (const uint4*)g_packed[tlist];
    for (int i = threadIdx.x; i < 2 * NREC; i += QTHREADS)
        dst[i] = src[i];
    unsigned short* sstart = (unsigned short*)(smraw + NREC * 32);
    for (int c = threadIdx.x; c <= NB; c += QTHREADS)
        sstart[c] = g_start[tlist][c];
    __syncthreads();

    const ulonglong2* recs = (const ulonglong2*)smraw;

    // warp w owns query-group (blockIdx.x + NCHUNK*w): 64 consecutive
    // sorted queries; lane k holds base+k and base+32+k.
    const int lwid = threadIdx.x >> 5;
    const int lane = threadIdx.x & 31;
    const int qgrp = blockIdx.x + NCHUNK * lwid;
    const int qbase = qgrp * (32 * QPT);

    float qx[QPT], q2[QPT], mlo[QPT], mhi[QPT];
    uint64_t nx[QPT], ny[QPT], nz[QPT];
    bool act[QPT];
    int bmin = 0x7fffffff, bmax = -1;
#pragma unroll
    for (int k = 0; k < QPT; k++) {
        int qi = qbase + 32 * k + lane;
        act[k] = (qi < nq);
        float a = 0.f, b = 0.f, c = 0.f;
        if (act[k]) {
            const float* qr = &g_packed[qlist][(qi >> 1) * 8];
            int s = qi & 1;
            a = qr[0 + s]; b = qr[2 + s]; c = qr[4 + s];
            int qb = min(max(__float2int_rd((a - GRIDMIN) * INVBW), 0), NB - 1);
            bmin = min(bmin, qb);
            bmax = max(bmax, qb);
        }
        qx[k] = a;
        q2[k] = a * a + b * b + c * c;
        nx[k] = pack2(-a, -a);
        ny[k] = pack2(-b, -b);
        nz[k] = pack2(-c, -c);
        mlo[k] = 3.0e37f;
        mhi[k] = 3.0e37f;
    }

    // warp-union window (warp-uniform); inactive lanes neutral
    int BL = bmin, BR = bmax;
#pragma unroll
    for (int off = 16; off; off >>= 1) {
        BL = min(BL, __shfl_xor_sync(0xffffffffu, BL, off));
        BR = max(BR, __shfl_xor_sync(0xffffffffu, BR, off));
    }

    if (BR >= 0) {  // warp has at least one active lane
        BL = max(BL - 3, 0);
        BR = min(BR + 4, NB);

        int LO = sstart[BL] & ~1;
        int HI = (sstart[BR] + 1) & ~1;
        scan_range(LO, HI, nx, ny, nz, recs, mlo, mhi);

        // ---- ballot-driven warp-uniform expansion ----
        for (int iter = 0; iter < NB; iter++) {
            bool needL = false, needR = false;
            float lbx = GRIDMIN + BL * BW;
            float rbx = GRIDMIN + BR * BW;
#pragma unroll
            for (int k = 0; k < QPT; k++) {
                float best = fmaxf(fmaf(2.0f, fminf(mlo[k], mhi[k]), q2[k]), 0.0f);
                float lb = fmaxf(qx[k] - lbx - 1e-4f, 0.0f);
                float rb = fmaxf(rbx - qx[k] - 1e-4f, 0.0f);
                needL |= act[k] && (lb * lb < best);
                needR |= act[k] && (rb * rb < best);
            }
            needL = needL && (BL > 0);
            needR = needR && (BR < NB);
            unsigned anyL = __ballot_sync(0xffffffffu, needL);
            unsigned anyR = __ballot_sync(0xffffffffu, needR);
            if (!anyL && !anyR) break;
            if (anyL) {
                int nBL = BL - 1;
                int nLO = sstart[nBL] & ~1;
                scan_range(nLO, LO, nx, ny, nz, recs, mlo, mhi);
                BL = nBL; LO = nLO;
            }
            if (anyR) {
                int nBR = BR + 1;
                int nHI = (sstart[nBR] + 1) & ~1;
                scan_range(HI, nHI, nx, ny, nz, recs, mlo, mhi);
                BR = nBR; HI = nHI;
            }
        }
    }

    float lsum = 0.f;
#pragma unroll
    for (int k = 0; k < QPT; k++)
        if (act[k])
            lsum += fmaxf(fmaf(2.0f, fminf(mlo[k], mhi[k]), q2[k]), 0.0f);

    // ---- block reduce + one atomicAdd ----
#pragma unroll
    for (int off = 16; off; off >>= 1)
        lsum += __shfl_down_sync(0xffffffffu, lsum, off);
    __shared__ float red[QTHREADS / 32];
    if ((threadIdx.x & 31) == 0) red[lwid] = lsum;
    __syncthreads();
    if (threadIdx.x == 0) {
        float tot = 0.f;
#pragma unroll
        for (int w = 0; w < QTHREADS / 32; w++) tot += red[w];
        int b = pair / SDIM;
        int s = pair % SDIM;
        atomicAdd(out + s * BDIM + b, tot / (float)nq);
    }
}

extern "C" void kernel_launch(void* const* d_in, const int* in_sizes, int n_in,
                              void* d_out, int out_size) {
    const float* outp = (const float*)d_in[0];  // [B,S,N,3]
    const float* tgtp = (const float*)d_in[1];  // [B,S,M,3]
    float* out = (float*)d_out;                  // [S,B]

    const int Nq = in_sizes[0] / (NPAIRS * 3);
    const int Mt = in_sizes[1] / (NPAIRS * 3);

    build_sorted<<<2 * NPAIRS, NB>>>(outp, tgtp, Nq, Mt, out);

    const size_t smem = (size_t)NREC * 32 + (NB + 2) * sizeof(unsigned short);
    cudaFuncSetAttribute(chamfer_query,
                         cudaFuncAttributeMaxDynamicSharedMemorySize, (int)smem);

    // NCHUNK blocks per (dir,pair); 8 warps/block stride the sorted order
    dim3 grid(NCHUNK, NPAIRS, 2);  // 256 blocks of 256 threads
    chamfer_query<<<grid, QTHREADS, smem>>>(Nq, Mt, out);
}